// round 1
// baseline (speedup 1.0000x reference)
#include <cuda_runtime.h>
#include <math.h>

#define Hh 100
#define Ww 100
#define FX 86.6f
#define NEAR_ 2.0f
#define FAR_ 6.0f
#define DINF 1e10f
#define NS 64
#define HID 256
#define HID_DIR 128
#define D_PTS 63
#define D_DIR 27

__device__ float g_z[NS];
__device__ float g_dists[NS];

// ---- shared memory layout (in floats) ----
#define S_ENC   0                      // 64 x 64 (D_PTS padded to 64)
#define S_H1    (S_ENC + 64*64)        // 64 x 256
#define S_H2    (S_H1 + 64*256)        // 64 x 256
#define S_HD    (S_H2 + 64*256)        // 64 x 128
#define S_WSIG  (S_HD + 64*128)        // 256
#define S_WRGB  (S_WSIG + 256)         // 384
#define S_EDIR  (S_WRGB + 384)         // 32 (27 used)
#define S_DC    (S_EDIR + 32)          // 128
#define S_SIG   (S_DC + 128)           // 64
#define S_RGB   (S_SIG + 64)           // 192
#define S_RAY   (S_RGB + 192)          // 16: [0..2]=o [3..5]=d [6..8]=v [9]=norm
#define SMEM_FLOATS (S_RAY + 16)
#define SMEM_BYTES  (SMEM_FLOATS * 4)

__global__ void precompute_kernel(const float* __restrict__ t_rand) {
    __shared__ float zsh[NS];
    int i = threadIdx.x;
    float t  = (float)i / 63.0f;
    float z0 = NEAR_ * (1.0f - t) + FAR_ * t;
    float tn = (float)(i + 1) / 63.0f;
    float z0n = NEAR_ * (1.0f - tn) + FAR_ * tn;
    float tp = (float)(i - 1) / 63.0f;
    float z0p = NEAR_ * (1.0f - tp) + FAR_ * tp;
    float mid_next = 0.5f * (z0 + z0n);
    float mid_prev = 0.5f * (z0p + z0);
    float upper = (i < NS - 1) ? mid_next : z0;
    float lower = (i > 0) ? mid_prev : z0;
    float z = lower + (upper - lower) * t_rand[i];
    zsh[i] = z;
    g_z[i] = z;
    __syncthreads();
    g_dists[i] = (i < NS - 1) ? (zsh[i + 1] - zsh[i]) : DINF;
}

__global__ __launch_bounds__(256, 1) void nerf_main(
    const float* __restrict__ c2w,
    const float* __restrict__ w1,   const float* __restrict__ b1,
    const float* __restrict__ w2,   const float* __restrict__ b2,
    const float* __restrict__ w_sig,const float* __restrict__ b_sig,
    const float* __restrict__ w_dir,const float* __restrict__ b_dir,
    const float* __restrict__ w_rgb,const float* __restrict__ b_rgb,
    float* __restrict__ out)
{
    extern __shared__ float sm[];
    const int tid = threadIdx.x;
    const int ray = blockIdx.x;

    // stage small weight vectors
    sm[S_WSIG + tid] = w_sig[tid];
    for (int t = tid; t < 384; t += 256) sm[S_WRGB + t] = w_rgb[t];

    if (tid == 0) {
        int c = ray % Ww, r = ray / Ww;
        float dx = ((float)c - 50.0f) / FX;
        float dy = -(((float)r - 50.0f) / FX);
        float dz = -1.0f;
        float d0 = dx * c2w[0] + dy * c2w[1] + dz * c2w[2];
        float d1 = dx * c2w[4] + dy * c2w[5] + dz * c2w[6];
        float d2 = dx * c2w[8] + dy * c2w[9] + dz * c2w[10];
        float nrm = sqrtf(d0 * d0 + d1 * d1 + d2 * d2);
        sm[S_RAY + 0] = c2w[3];  sm[S_RAY + 1] = c2w[7];  sm[S_RAY + 2] = c2w[11];
        sm[S_RAY + 3] = d0;      sm[S_RAY + 4] = d1;      sm[S_RAY + 5] = d2;
        sm[S_RAY + 6] = d0 / nrm; sm[S_RAY + 7] = d1 / nrm; sm[S_RAY + 8] = d2 / nrm;
        sm[S_RAY + 9] = nrm;
    }
    __syncthreads();

    // enc_dir (27)
    if (tid < D_DIR) {
        float val;
        if (tid < 3) val = sm[S_RAY + 6 + tid];
        else {
            int t = tid - 3; int l = t / 6; int r6 = t % 6; int cc = r6 % 3;
            float x = sm[S_RAY + 6 + cc] * (float)(1 << l);
            val = (r6 < 3) ? sinf(x) : cosf(x);
        }
        sm[S_EDIR + tid] = val;
    }

    // enc_pts: 64 samples x 63 dims
    {
        float o0 = sm[S_RAY + 0], o1 = sm[S_RAY + 1], o2 = sm[S_RAY + 2];
        float d0 = sm[S_RAY + 3], d1 = sm[S_RAY + 4], d2 = sm[S_RAY + 5];
        for (int idx = tid; idx < NS * D_PTS; idx += 256) {
            int s = idx / D_PTS;
            int dd = idx - s * D_PTS;
            float z = g_z[s];
            int cc = (dd < 3) ? dd : ((dd - 3) % 6) % 3;
            float pt = (cc == 0) ? fmaf(d0, z, o0) : (cc == 1) ? fmaf(d1, z, o1) : fmaf(d2, z, o2);
            float val;
            if (dd < 3) val = pt;
            else {
                int t = dd - 3; int l = t / 6; int r6 = t % 6;
                float x = pt * (float)(1 << l);
                val = (r6 < 3) ? sinf(x) : cosf(x);
            }
            sm[S_ENC + s * 64 + dd] = val;
        }
        if (tid < NS) sm[S_ENC + tid * 64 + 63] = 0.0f;  // pad
    }
    __syncthreads();

    // ---------- GEMM1: h1[64][256] = relu(enc @ w1 + b1) ----------
    {
        const int j = tid;
        float wr[64];
        #pragma unroll
        for (int k = 0; k < 63; k++) wr[k] = w1[k * 256 + j];
        wr[63] = 0.0f;
        float bj = b1[j];
        #pragma unroll 1
        for (int p = 0; p < NS; p += 2) {
            float a0 = bj, a1 = bj;
            const float4* e0 = (const float4*)(sm + S_ENC + p * 64);
            const float4* e1 = (const float4*)(sm + S_ENC + (p + 1) * 64);
            #pragma unroll
            for (int kk = 0; kk < 16; kk++) {
                float4 u = e0[kk], v = e1[kk];
                a0 = fmaf(u.x, wr[4*kk+0], a0); a1 = fmaf(v.x, wr[4*kk+0], a1);
                a0 = fmaf(u.y, wr[4*kk+1], a0); a1 = fmaf(v.y, wr[4*kk+1], a1);
                a0 = fmaf(u.z, wr[4*kk+2], a0); a1 = fmaf(v.z, wr[4*kk+2], a1);
                a0 = fmaf(u.w, wr[4*kk+3], a0); a1 = fmaf(v.w, wr[4*kk+3], a1);
            }
            sm[S_H1 + p * 256 + j]       = fmaxf(a0, 0.0f);
            sm[S_H1 + (p + 1) * 256 + j] = fmaxf(a1, 0.0f);
        }
    }
    __syncthreads();

    // ---------- GEMM2: h2[64][256] = relu(h1 @ w2 + b2) ----------
    {
        const int j = tid;
        const float bj = b2[j];
        #pragma unroll 1
        for (int kc = 0; kc < 4; kc++) {
            float wr[64];
            #pragma unroll
            for (int k = 0; k < 64; k++) wr[k] = w2[(kc * 64 + k) * 256 + j];
            #pragma unroll 1
            for (int p = 0; p < NS; p += 2) {
                float a0 = (kc == 0) ? bj : sm[S_H2 + p * 256 + j];
                float a1 = (kc == 0) ? bj : sm[S_H2 + (p + 1) * 256 + j];
                const float4* e0 = (const float4*)(sm + S_H1 + p * 256 + kc * 64);
                const float4* e1 = (const float4*)(sm + S_H1 + (p + 1) * 256 + kc * 64);
                #pragma unroll
                for (int kk = 0; kk < 16; kk++) {
                    float4 u = e0[kk], v = e1[kk];
                    a0 = fmaf(u.x, wr[4*kk+0], a0); a1 = fmaf(v.x, wr[4*kk+0], a1);
                    a0 = fmaf(u.y, wr[4*kk+1], a0); a1 = fmaf(v.y, wr[4*kk+1], a1);
                    a0 = fmaf(u.z, wr[4*kk+2], a0); a1 = fmaf(v.z, wr[4*kk+2], a1);
                    a0 = fmaf(u.w, wr[4*kk+3], a0); a1 = fmaf(v.w, wr[4*kk+3], a1);
                }
                if (kc == 3) { a0 = fmaxf(a0, 0.0f); a1 = fmaxf(a1, 0.0f); }
                sm[S_H2 + p * 256 + j] = a0;
                sm[S_H2 + (p + 1) * 256 + j] = a1;
            }
        }
    }
    __syncthreads();

    // dir-encoding rank-1 contribution (per hidden-dir unit) + sigma head
    if (tid < HID_DIR) {
        int j = tid;
        float acc = b_dir[j];
        #pragma unroll
        for (int dd = 0; dd < D_DIR; dd++)
            acc = fmaf(sm[S_EDIR + dd], w_dir[(256 + dd) * HID_DIR + j], acc);
        sm[S_DC + j] = acc;
    } else if (tid < 192) {
        int p = tid - 128;
        float acc = b_sig[0];
        const float4* h = (const float4*)(sm + S_H2 + p * 256);
        const float4* ws = (const float4*)(sm + S_WSIG);
        #pragma unroll 8
        for (int k = 0; k < 64; k++) {
            float4 a = h[k], b = ws[k];
            acc = fmaf(a.x, b.x, acc); acc = fmaf(a.y, b.y, acc);
            acc = fmaf(a.z, b.z, acc); acc = fmaf(a.w, b.w, acc);
        }
        sm[S_SIG + p] = acc;
    }
    __syncthreads();

    // ---------- GEMM3: hd[64][128] = relu(h2 @ w_dir[0:256] + dc) ----------
    {
        const int j = tid & 127;
        const int p0 = (tid >> 7) * 32;
        #pragma unroll 1
        for (int kc = 0; kc < 4; kc++) {
            float wr[64];
            #pragma unroll
            for (int k = 0; k < 64; k++) wr[k] = w_dir[(kc * 64 + k) * HID_DIR + j];
            #pragma unroll 1
            for (int p = p0; p < p0 + 32; p += 2) {
                float a0 = (kc == 0) ? sm[S_DC + j] : sm[S_HD + p * 128 + j];
                float a1 = (kc == 0) ? sm[S_DC + j] : sm[S_HD + (p + 1) * 128 + j];
                const float4* e0 = (const float4*)(sm + S_H2 + p * 256 + kc * 64);
                const float4* e1 = (const float4*)(sm + S_H2 + (p + 1) * 256 + kc * 64);
                #pragma unroll
                for (int kk = 0; kk < 16; kk++) {
                    float4 u = e0[kk], v = e1[kk];
                    a0 = fmaf(u.x, wr[4*kk+0], a0); a1 = fmaf(v.x, wr[4*kk+0], a1);
                    a0 = fmaf(u.y, wr[4*kk+1], a0); a1 = fmaf(v.y, wr[4*kk+1], a1);
                    a0 = fmaf(u.z, wr[4*kk+2], a0); a1 = fmaf(v.z, wr[4*kk+2], a1);
                    a0 = fmaf(u.w, wr[4*kk+3], a0); a1 = fmaf(v.w, wr[4*kk+3], a1);
                }
                if (kc == 3) { a0 = fmaxf(a0, 0.0f); a1 = fmaxf(a1, 0.0f); }
                sm[S_HD + p * 128 + j] = a0;
                sm[S_HD + (p + 1) * 128 + j] = a1;
            }
        }
    }
    __syncthreads();

    // rgb head: 64 points x 3 channels
    if (tid < 192) {
        int p = tid / 3, cc = tid - p * 3;
        float acc = b_rgb[cc];
        #pragma unroll 8
        for (int k = 0; k < HID_DIR; k++)
            acc = fmaf(sm[S_HD + p * 128 + k], sm[S_WRGB + k * 3 + cc], acc);
        sm[S_RGB + tid] = 1.0f / (1.0f + expf(-acc));
    }
    __syncthreads();

    // compositing (serial scan over samples)
    if (tid == 0) {
        float nrm = sm[S_RAY + 9];
        float T = 1.0f, r = 0.0f, g = 0.0f, b = 0.0f;
        #pragma unroll 1
        for (int s = 0; s < NS; s++) {
            float sg = fmaxf(sm[S_SIG + s], 0.0f);
            float a = 1.0f - expf(-sg * g_dists[s] * nrm);
            float w = a * T;
            r = fmaf(w, sm[S_RGB + s * 3 + 0], r);
            g = fmaf(w, sm[S_RGB + s * 3 + 1], g);
            b = fmaf(w, sm[S_RGB + s * 3 + 2], b);
            T *= (1.0f - a);
        }
        out[ray * 3 + 0] = r;
        out[ray * 3 + 1] = g;
        out[ray * 3 + 2] = b;
    }
}

extern "C" void kernel_launch(void* const* d_in, const int* in_sizes, int n_in,
                              void* d_out, int out_size) {
    const float* c2w    = (const float*)d_in[0];
    const float* t_rand = (const float*)d_in[1];
    const float* w1     = (const float*)d_in[2];
    const float* b1     = (const float*)d_in[3];
    const float* w2     = (const float*)d_in[4];
    const float* b2     = (const float*)d_in[5];
    const float* w_sig  = (const float*)d_in[6];
    const float* b_sig  = (const float*)d_in[7];
    const float* w_dir  = (const float*)d_in[8];
    const float* b_dir  = (const float*)d_in[9];
    const float* w_rgb  = (const float*)d_in[10];
    const float* b_rgb  = (const float*)d_in[11];
    float* out = (float*)d_out;

    cudaFuncSetAttribute(nerf_main, cudaFuncAttributeMaxDynamicSharedMemorySize, SMEM_BYTES);

    precompute_kernel<<<1, NS>>>(t_rand);
    nerf_main<<<Hh * Ww, 256, SMEM_BYTES>>>(c2w, w1, b1, w2, b2, w_sig, b_sig,
                                            w_dir, b_dir, w_rgb, b_rgb, out);
}

// round 3
// speedup vs baseline: 3.2599x; 3.2599x over previous
#include <cuda_runtime.h>
#include <cuda_bf16.h>
#include <stdint.h>
#include <math.h>

#define NSAMP 64
#define NBLOCKS 5000           // 2 rays per block, M = 128 sample-rows
#define FXc 86.6f
#define NEAR_ 2.0f
#define FAR_ 6.0f
#define DINF 1e10f

// ---------------- global scratch (weights pre-split to bf16 hi/lo, [N][K]) ----------------
__device__ float g_z[NSAMP];
__device__ float g_dists[NSAMP];
__device__ __align__(16) __nv_bfloat16 g_w1T_hi[256 * 64],  g_w1T_lo[256 * 64];
__device__ __align__(16) __nv_bfloat16 g_w2T_hi[256 * 256], g_w2T_lo[256 * 256];
__device__ __align__(16) __nv_bfloat16 g_wdT_hi[128 * 256], g_wdT_lo[128 * 256];

// ---------------- smem layout (bytes) ----------------
// [0, 8192)        misc floats
// [8192, 75776)    A hi plane:  128 rows x 264 bf16 (row stride 528 B)
// [75776, 143360)  A lo plane
// [143360, 225280) B stages: 2 x { hi plane 20480 B, lo plane 20480 B }, rows padded to 40 bf16
#define A_HI_OFF  8192u
#define A_LO_OFF  75776u
#define B_OFF     143360u
#define STAGE_B   40960u
#define PLANE_B   20480u
#define AROW      528u
#define SMEM_BYTES 225280

// misc float offsets
#define F_RAY   0      // [2][12]: o(3) d(3) v(3) norm
#define F_B1    32
#define F_B2    288
#define F_WSIG  544
#define F_WRGB  800    // 384
#define F_EDIR  1184   // [2][32]
#define F_DC    1248   // [2][128]
#define F_SIG   1504   // [128]
#define F_RGB   1632   // [128][3]

// ---------------- small asm helpers (all sm_80-era PTX; no 'a'-gated features) -------------
__device__ __forceinline__ uint32_t smem_u32(const void* p) {
    uint32_t a;
    asm("{ .reg .u64 t; cvta.to.shared.u64 t, %1; cvt.u32.u64 %0, t; }" : "=r"(a) : "l"(p));
    return a;
}
__device__ __forceinline__ uint32_t lds32(uint32_t a) {
    uint32_t v; asm volatile("ld.shared.b32 %0, [%1];" : "=r"(v) : "r"(a)); return v;
}
__device__ __forceinline__ void sts32(uint32_t a, uint32_t v) {
    asm volatile("st.shared.b32 [%0], %1;" :: "r"(a), "r"(v));
}
__device__ __forceinline__ void mma_bf16(float* c, const uint32_t* a, uint32_t b0, uint32_t b1) {
    asm volatile(
        "mma.sync.aligned.m16n8k16.row.col.f32.bf16.bf16.f32 "
        "{%0,%1,%2,%3}, {%4,%5,%6,%7}, {%8,%9}, {%0,%1,%2,%3};"
        : "+f"(c[0]), "+f"(c[1]), "+f"(c[2]), "+f"(c[3])
        : "r"(a[0]), "r"(a[1]), "r"(a[2]), "r"(a[3]), "r"(b0), "r"(b1));
}
__device__ __forceinline__ void cpa16(uint32_t d, const void* s) {
    asm volatile("cp.async.ca.shared.global [%0], [%1], 16;" :: "r"(d), "l"(s));
}
#define CP_COMMIT() asm volatile("cp.async.commit_group;" ::: "memory")
#define CP_WAIT1()  asm volatile("cp.async.wait_group 1;" ::: "memory")

__device__ __forceinline__ void split2(float a, float b, uint32_t& hi, uint32_t& lo) {
    __nv_bfloat16 ha = __float2bfloat16(a), hb = __float2bfloat16(b);
    __nv_bfloat16 la = __float2bfloat16(a - __bfloat162float(ha));
    __nv_bfloat16 lb = __float2bfloat16(b - __bfloat162float(hb));
    __nv_bfloat162 th = __halves2bfloat162(ha, hb), tl = __halves2bfloat162(la, lb);
    hi = *reinterpret_cast<uint32_t*>(&th);
    lo = *reinterpret_cast<uint32_t*>(&tl);
}
__device__ __forceinline__ float qred(float v) {
    v += __shfl_xor_sync(0xffffffffu, v, 1);
    v += __shfl_xor_sync(0xffffffffu, v, 2);
    return v;
}

// fill one K=32 chunk: rows [0,nrows) of [N][K] hi/lo planes -> stage (rows padded to 40 elems)
__device__ __forceinline__ void cp_fill(uint32_t dst, const __nv_bfloat16* __restrict__ hi,
                                        const __nv_bfloat16* __restrict__ lo,
                                        int nrows, int kstride, int kbase, int tid) {
    int total = nrows * 4;
    for (int i = tid; i < total; i += 256) {
        int n = i >> 2, seg = i & 3;
        uint32_t d = dst + (uint32_t)n * 80u + (uint32_t)seg * 16u;
        cpa16(d,            (const char*)(hi + n * kstride + kbase) + seg * 16);
        cpa16(d + PLANE_B,  (const char*)(lo + n * kstride + kbase) + seg * 16);
    }
}

// GEMM over M=128 (8 warps x 16 rows), N = NT*8, K = nchunks*32, 3-product bf16 split.
// Protocol: two chunk-groups pre-committed by caller; each iter: wait<=1, sync, compute,
// sync, commit next (possibly empty) group.
template<int NT>
__device__ __forceinline__ void gemm_run(float (*C)[4], int nchunks, int nrows_b,
                                         const __nv_bfloat16* __restrict__ shi,
                                         const __nv_bfloat16* __restrict__ slo,
                                         int kstride, uint32_t aHi, uint32_t aLo,
                                         uint32_t bBase, int tid) {
    const int lane = tid & 31, wid = tid >> 5;
    const uint32_t arow = (uint32_t)(16 * wid + (lane >> 2)) * AROW + (uint32_t)(lane & 3) * 4u;
    const uint32_t brow = (uint32_t)(lane >> 2) * 80u + (uint32_t)(lane & 3) * 4u;
    #pragma unroll
    for (int t = 0; t < NT; t++) { C[t][0] = 0.f; C[t][1] = 0.f; C[t][2] = 0.f; C[t][3] = 0.f; }
    #pragma unroll 1
    for (int ch = 0; ch < nchunks; ch++) {
        CP_WAIT1();
        __syncthreads();
        uint32_t bs = bBase + (uint32_t)(ch & 1) * STAGE_B;
        #pragma unroll
        for (int k16 = 0; k16 < 2; k16++) {
            uint32_t kb = (uint32_t)(ch * 32 + k16 * 16) * 2u;
            uint32_t ah = aHi + arow + kb, al = aLo + arow + kb;
            uint32_t a_hi[4], a_lo[4];
            a_hi[0] = lds32(ah);                a_hi[1] = lds32(ah + 8 * AROW);
            a_hi[2] = lds32(ah + 16);           a_hi[3] = lds32(ah + 8 * AROW + 16);
            a_lo[0] = lds32(al);                a_lo[1] = lds32(al + 8 * AROW);
            a_lo[2] = lds32(al + 16);           a_lo[3] = lds32(al + 8 * AROW + 16);
            uint32_t bk = bs + brow + (uint32_t)k16 * 32u;
            #pragma unroll
            for (int nt = 0; nt < NT; nt++) {
                uint32_t ba = bk + (uint32_t)nt * 640u;
                uint32_t bh0 = lds32(ba),            bh1 = lds32(ba + 16);
                uint32_t bl0 = lds32(ba + PLANE_B),  bl1 = lds32(ba + PLANE_B + 16);
                mma_bf16(C[nt], a_hi, bh0, bh1);
                mma_bf16(C[nt], a_hi, bl0, bl1);
                mma_bf16(C[nt], a_lo, bh0, bh1);
            }
        }
        __syncthreads();
        if (ch + 2 < nchunks)
            cp_fill(bBase + (uint32_t)(ch & 1) * STAGE_B, shi, slo, nrows_b, kstride,
                    (ch + 2) * 32, tid);
        CP_COMMIT();
    }
}

// ---------------- aux kernels ----------------
__global__ void precompute_kernel(const float* __restrict__ t_rand) {
    __shared__ float zsh[NSAMP];
    int i = threadIdx.x;
    float t   = (float)i / 63.0f;
    float z0  = NEAR_ * (1.0f - t) + FAR_ * t;
    float tn  = (float)(i + 1) / 63.0f;
    float z0n = NEAR_ * (1.0f - tn) + FAR_ * tn;
    float tp  = (float)(i - 1) / 63.0f;
    float z0p = NEAR_ * (1.0f - tp) + FAR_ * tp;
    float upper = (i < NSAMP - 1) ? 0.5f * (z0 + z0n) : z0;
    float lower = (i > 0) ? 0.5f * (z0p + z0) : z0;
    float z = lower + (upper - lower) * t_rand[i];
    zsh[i] = z;
    g_z[i] = z;
    __syncthreads();
    g_dists[i] = (i < NSAMP - 1) ? (zsh[i + 1] - zsh[i]) : DINF;
}

__global__ void prep_weights(const float* __restrict__ w1,
                             const float* __restrict__ w2,
                             const float* __restrict__ wd) {
    int idx = blockIdx.x * 256 + threadIdx.x;
    float v; __nv_bfloat16 *ph, *pl; int o;
    if (idx < 16384) {
        int n = idx >> 6, k = idx & 63;
        v = (k < 63) ? w1[k * 256 + n] : 0.0f;
        ph = g_w1T_hi; pl = g_w1T_lo; o = idx;
    } else if (idx < 16384 + 65536) {
        int t = idx - 16384; int n = t >> 8, k = t & 255;
        v = w2[k * 256 + n];
        ph = g_w2T_hi; pl = g_w2T_lo; o = t;
    } else if (idx < 16384 + 65536 + 32768) {
        int t = idx - 16384 - 65536; int n = t >> 8, k = t & 255;
        v = wd[k * 128 + n];
        ph = g_wdT_hi; pl = g_wdT_lo; o = t;
    } else return;
    __nv_bfloat16 h = __float2bfloat16(v);
    ph[o] = h;
    pl[o] = __float2bfloat16(v - __bfloat162float(h));
}

// ---------------- main fused kernel ----------------
__global__ void __launch_bounds__(256, 1) nerf_hmma(
    const float* __restrict__ c2w,
    const float* __restrict__ b1g,  const float* __restrict__ b2g,
    const float* __restrict__ wsigg,const float* __restrict__ bsigg,
    const float* __restrict__ wdirg,const float* __restrict__ bdirg,
    const float* __restrict__ wrgbg,const float* __restrict__ brgbg,
    float* __restrict__ out)
{
    extern __shared__ char smraw[];
    float* smf = (float*)smraw;
    const uint32_t base = smem_u32(smraw);
    const uint32_t aHi = base + A_HI_OFF, aLo = base + A_LO_OFF, bB = base + B_OFF;
    const int tid = threadIdx.x, lane = tid & 31, wid = tid >> 5;
    const int ray0 = blockIdx.x * 2;

    // prefetch GEMM1's two K-chunks of w1T immediately (2 groups)
    cp_fill(bB,           g_w1T_hi, g_w1T_lo, 256, 64, 0,  tid); CP_COMMIT();
    cp_fill(bB + STAGE_B, g_w1T_hi, g_w1T_lo, 256, 64, 32, tid); CP_COMMIT();

    // stage small tensors
    for (int i = tid; i < 256; i += 256) {
        smf[F_B1 + i]   = b1g[i];
        smf[F_B2 + i]   = b2g[i];
        smf[F_WSIG + i] = wsigg[i];
    }
    for (int i = tid; i < 384; i += 256) smf[F_WRGB + i] = wrgbg[i];
    if (tid < 2) {
        int ray = ray0 + tid;
        int c = ray % 100, rw = ray / 100;
        float dx = ((float)c - 50.0f) / FXc;
        float dy = -(((float)rw - 50.0f) / FXc);
        float d0 = dx * c2w[0] + dy * c2w[1] - c2w[2];
        float d1 = dx * c2w[4] + dy * c2w[5] - c2w[6];
        float d2 = dx * c2w[8] + dy * c2w[9] - c2w[10];
        float nrm = sqrtf(d0 * d0 + d1 * d1 + d2 * d2);
        float* R = smf + F_RAY + tid * 12;
        R[0] = c2w[3]; R[1] = c2w[7]; R[2] = c2w[11];
        R[3] = d0; R[4] = d1; R[5] = d2;
        R[6] = d0 / nrm; R[7] = d1 / nrm; R[8] = d2 / nrm;
        R[9] = nrm;
    }
    __syncthreads();

    // enc_dir (27 per ray)
    if (tid < 54) {
        int rr = tid / 27, dd = tid - rr * 27;
        const float* vv = smf + F_RAY + rr * 12 + 6;
        float val;
        if (dd < 3) val = vv[dd];
        else {
            int u = dd - 3, l = u / 6, r6 = u % 6, cc = r6 % 3;
            float x = vv[cc] * (float)(1 << l);
            val = (r6 < 3) ? sinf(x) : cosf(x);
        }
        smf[F_EDIR + rr * 32 + dd] = val;
    }

    // posenc(pts): 128 rows x 63 dims -> A planes (cols 0..63, col 63 zero)
    if (tid < 128) {
        int rr = tid >> 6, s = tid & 63;
        float z = g_z[s];
        const float* R = smf + F_RAY + rr * 12;
        float v[64];
        float f0 = fmaf(R[3], z, R[0]);
        float f1 = fmaf(R[4], z, R[1]);
        float f2 = fmaf(R[5], z, R[2]);
        v[0] = f0; v[1] = f1; v[2] = f2;
        #pragma unroll
        for (int l = 0; l < 10; l++) {
            float s0, c0, s1, c1, s2, c2;
            sincosf(f0, &s0, &c0); sincosf(f1, &s1, &c1); sincosf(f2, &s2, &c2);
            int b = 3 + l * 6;
            v[b] = s0; v[b + 1] = s1; v[b + 2] = s2;
            v[b + 3] = c0; v[b + 4] = c1; v[b + 5] = c2;
            f0 *= 2.0f; f1 *= 2.0f; f2 *= 2.0f;
        }
        v[63] = 0.0f;
        uint32_t hi2[32], lo2[32];
        #pragma unroll
        for (int i = 0; i < 32; i++) split2(v[2 * i], v[2 * i + 1], hi2[i], lo2[i]);
        uint32_t ro = (uint32_t)tid * AROW;
        const uint4* h4 = (const uint4*)hi2;
        const uint4* l4 = (const uint4*)lo2;
        #pragma unroll
        for (int q = 0; q < 8; q++) {
            *(uint4*)(smraw + (A_HI_OFF + ro) + q * 16) = h4[q];
            *(uint4*)(smraw + (A_LO_OFF + ro) + q * 16) = l4[q];
        }
    }
    // (gemm_run's first internal barrier orders enc writes vs fragment reads)

    float C[32][4];

    // ---------------- GEMM1: h1 = relu(enc @ w1 + b1), N=256, K=64 ----------------
    gemm_run<32>(C, 2, 256, g_w1T_hi, g_w1T_lo, 64, aHi, aLo, bB, tid);
    {   // epilogue: bias+relu+split -> A planes (all reads done at loop's trailing barrier)
        #pragma unroll
        for (int nt = 0; nt < 32; nt++) {
            int col = nt * 8 + 2 * (lane & 3);
            float2 bb = *(float2*)(smf + F_B1 + col);
            float v0 = fmaxf(C[nt][0] + bb.x, 0.f), v1 = fmaxf(C[nt][1] + bb.y, 0.f);
            float v2 = fmaxf(C[nt][2] + bb.x, 0.f), v3 = fmaxf(C[nt][3] + bb.y, 0.f);
            uint32_t h0, l0, h1w, l1w;
            split2(v0, v1, h0, l0); split2(v2, v3, h1w, l1w);
            uint32_t o0 = (uint32_t)(16 * wid + (lane >> 2)) * AROW + (uint32_t)col * 2u;
            uint32_t o1 = o0 + 8 * AROW;
            sts32(aHi + o0, h0);  sts32(aLo + o0, l0);
            sts32(aHi + o1, h1w); sts32(aLo + o1, l1w);
        }
    }
    // prefetch GEMM2 chunks 0,1
    cp_fill(bB,           g_w2T_hi, g_w2T_lo, 256, 256, 0,  tid); CP_COMMIT();
    cp_fill(bB + STAGE_B, g_w2T_hi, g_w2T_lo, 256, 256, 32, tid); CP_COMMIT();
    // dir-head rank-1 bias dc[2][128] (overlaps with prefetch latency)
    {
        int j = tid & 127, rr = tid >> 7;
        float acc = bdirg[j];
        #pragma unroll
        for (int dd = 0; dd < 27; dd++)
            acc = fmaf(smf[F_EDIR + rr * 32 + dd], wdirg[(256 + dd) * 128 + j], acc);
        smf[F_DC + rr * 128 + j] = acc;
    }

    // ---------------- GEMM2: h2 = relu(h1 @ w2 + b2), N=256, K=256 ----------------
    gemm_run<32>(C, 8, 256, g_w2T_hi, g_w2T_lo, 256, aHi, aLo, bB, tid);
    {   // epilogue: bias+relu, fused sigma head, split -> A planes
        float sl = 0.f, sh = 0.f;
        #pragma unroll
        for (int nt = 0; nt < 32; nt++) {
            int col = nt * 8 + 2 * (lane & 3);
            float2 bb = *(float2*)(smf + F_B2 + col);
            float2 ws = *(float2*)(smf + F_WSIG + col);
            float v0 = fmaxf(C[nt][0] + bb.x, 0.f), v1 = fmaxf(C[nt][1] + bb.y, 0.f);
            float v2 = fmaxf(C[nt][2] + bb.x, 0.f), v3 = fmaxf(C[nt][3] + bb.y, 0.f);
            sl = fmaf(v0, ws.x, fmaf(v1, ws.y, sl));
            sh = fmaf(v2, ws.x, fmaf(v3, ws.y, sh));
            uint32_t h0, l0, h1w, l1w;
            split2(v0, v1, h0, l0); split2(v2, v3, h1w, l1w);
            uint32_t o0 = (uint32_t)(16 * wid + (lane >> 2)) * AROW + (uint32_t)col * 2u;
            uint32_t o1 = o0 + 8 * AROW;
            sts32(aHi + o0, h0);  sts32(aLo + o0, l0);
            sts32(aHi + o1, h1w); sts32(aLo + o1, l1w);
        }
        sl = qred(sl); sh = qred(sh);
        if ((lane & 3) == 0) {
            float bs0 = bsigg[0];
            smf[F_SIG + 16 * wid + (lane >> 2)]     = sl + bs0;
            smf[F_SIG + 16 * wid + (lane >> 2) + 8] = sh + bs0;
        }
    }
    // prefetch GEMM3 chunks 0,1
    cp_fill(bB,           g_wdT_hi, g_wdT_lo, 128, 256, 0,  tid); CP_COMMIT();
    cp_fill(bB + STAGE_B, g_wdT_hi, g_wdT_lo, 128, 256, 32, tid); CP_COMMIT();

    // ---------------- GEMM3: hd = relu(h2 @ w_dir[0:256] + dc), N=128, K=256 --------
    gemm_run<16>(C, 8, 128, g_wdT_hi, g_wdT_lo, 256, aHi, aLo, bB, tid);
    {   // epilogue: fused rgb head straight from fragments
        int row = 16 * wid + (lane >> 2);
        int ray = row >> 6;
        const float* dcp = smf + F_DC + ray * 128;
        float r0 = 0.f, g0 = 0.f, b0 = 0.f, r1 = 0.f, g1 = 0.f, b1v = 0.f;
        #pragma unroll
        for (int nt = 0; nt < 16; nt++) {
            int col = nt * 8 + 2 * (lane & 3);
            float d0 = dcp[col], d1 = dcp[col + 1];
            float h0 = fmaxf(C[nt][0] + d0, 0.f), h1 = fmaxf(C[nt][1] + d1, 0.f);
            float h2 = fmaxf(C[nt][2] + d0, 0.f), h3 = fmaxf(C[nt][3] + d1, 0.f);
            const float* w0 = smf + F_WRGB + col * 3;
            const float* w1v = w0 + 3;
            r0  = fmaf(h0, w0[0], fmaf(h1, w1v[0], r0));
            g0  = fmaf(h0, w0[1], fmaf(h1, w1v[1], g0));
            b0  = fmaf(h0, w0[2], fmaf(h1, w1v[2], b0));
            r1  = fmaf(h2, w0[0], fmaf(h3, w1v[0], r1));
            g1  = fmaf(h2, w0[1], fmaf(h3, w1v[1], g1));
            b1v = fmaf(h2, w0[2], fmaf(h3, w1v[2], b1v));
        }
        r0 = qred(r0); g0 = qred(g0); b0 = qred(b0);
        r1 = qred(r1); g1 = qred(g1); b1v = qred(b1v);
        if ((lane & 3) == 0) {
            float br = brgbg[0], bg = brgbg[1], bbv = brgbg[2];
            smf[F_RGB + row * 3 + 0] = 1.0f / (1.0f + expf(-(r0 + br)));
            smf[F_RGB + row * 3 + 1] = 1.0f / (1.0f + expf(-(g0 + bg)));
            smf[F_RGB + row * 3 + 2] = 1.0f / (1.0f + expf(-(b0 + bbv)));
            smf[F_RGB + (row + 8) * 3 + 0] = 1.0f / (1.0f + expf(-(r1 + br)));
            smf[F_RGB + (row + 8) * 3 + 1] = 1.0f / (1.0f + expf(-(g1 + bg)));
            smf[F_RGB + (row + 8) * 3 + 2] = 1.0f / (1.0f + expf(-(b1v + bbv)));
        }
    }
    __syncthreads();

    // ---------------- compositing (2 rays) ----------------
    if (tid < 2) {
        float nrm = smf[F_RAY + tid * 12 + 9];
        float T = 1.0f, r = 0.0f, g = 0.0f, b = 0.0f;
        #pragma unroll 1
        for (int s = 0; s < NSAMP; s++) {
            int m = tid * 64 + s;
            float sg = fmaxf(smf[F_SIG + m], 0.0f);
            float a = 1.0f - expf(-sg * g_dists[s] * nrm);
            float w = a * T;
            r = fmaf(w, smf[F_RGB + m * 3 + 0], r);
            g = fmaf(w, smf[F_RGB + m * 3 + 1], g);
            b = fmaf(w, smf[F_RGB + m * 3 + 2], b);
            T *= (1.0f - a);
        }
        out[(ray0 + tid) * 3 + 0] = r;
        out[(ray0 + tid) * 3 + 1] = g;
        out[(ray0 + tid) * 3 + 2] = b;
    }
}

extern "C" void kernel_launch(void* const* d_in, const int* in_sizes, int n_in,
                              void* d_out, int out_size) {
    const float* c2w    = (const float*)d_in[0];
    const float* t_rand = (const float*)d_in[1];
    const float* w1     = (const float*)d_in[2];
    const float* b1     = (const float*)d_in[3];
    const float* w2     = (const float*)d_in[4];
    const float* b2     = (const float*)d_in[5];
    const float* w_sig  = (const float*)d_in[6];
    const float* b_sig  = (const float*)d_in[7];
    const float* w_dir  = (const float*)d_in[8];
    const float* b_dir  = (const float*)d_in[9];
    const float* w_rgb  = (const float*)d_in[10];
    const float* b_rgb  = (const float*)d_in[11];
    float* out = (float*)d_out;

    cudaFuncSetAttribute(nerf_hmma, cudaFuncAttributeMaxDynamicSharedMemorySize, SMEM_BYTES);

    precompute_kernel<<<1, NSAMP>>>(t_rand);
    prep_weights<<<448, 256>>>(w1, w2, w_dir);
    nerf_hmma<<<NBLOCKS, 256, SMEM_BYTES>>>(c2w, b1, b2, w_sig, b_sig,
                                            w_dir, b_dir, w_rgb, b_rgb, out);
}

// round 4
// speedup vs baseline: 3.2599x; 1.0000x over previous
#include <cuda_runtime.h>
#include <cuda_bf16.h>
#include <stdint.h>
#include <math.h>

#define NSAMP 64
#define NBLOCKS 5000           // 2 rays per block, M = 128 sample-rows
#define FXc 86.6f
#define NEAR_ 2.0f
#define FAR_ 6.0f
#define DINF 1e10f

// ---------------- global scratch (weights pre-split to bf16 hi/lo, [N][K]) ----------------
__device__ float g_z[NSAMP];
__device__ float g_dists[NSAMP];
__device__ __align__(16) __nv_bfloat16 g_w1T_hi[256 * 64],  g_w1T_lo[256 * 64];
__device__ __align__(16) __nv_bfloat16 g_w2T_hi[256 * 256], g_w2T_lo[256 * 256];
__device__ __align__(16) __nv_bfloat16 g_wdT_hi[128 * 256], g_wdT_lo[128 * 256];

// ---------------- smem layout (bytes) ----------------
// [0, 8192)        misc floats
// [8192, 75776)    A hi plane:  128 rows x 264 bf16 (row stride 528 B)
// [75776, 143360)  A lo plane
// [143360, 225280) B stages: 2 x { hi plane 20480 B, lo plane 20480 B }, rows padded to 40 bf16
#define A_HI_OFF  8192u
#define A_LO_OFF  75776u
#define B_OFF     143360u
#define STAGE_B   40960u
#define PLANE_B   20480u
#define AROW      528u
#define SMEM_BYTES 225280

// misc float offsets
#define F_RAY   0      // [2][12]: o(3) d(3) v(3) norm
#define F_B1    32
#define F_B2    288
#define F_WSIG  544
#define F_WRGB  800    // 384
#define F_EDIR  1184   // [2][32]
#define F_DC    1248   // [2][128]
#define F_SIG   1504   // [128]
#define F_RGB   1632   // [128][3]

// ---------------- small asm helpers (all sm_80-era PTX; no 'a'-gated features) -------------
__device__ __forceinline__ uint32_t smem_u32(const void* p) {
    uint32_t a;
    asm("{ .reg .u64 t; cvta.to.shared.u64 t, %1; cvt.u32.u64 %0, t; }" : "=r"(a) : "l"(p));
    return a;
}
__device__ __forceinline__ uint32_t lds32(uint32_t a) {
    uint32_t v; asm volatile("ld.shared.b32 %0, [%1];" : "=r"(v) : "r"(a)); return v;
}
__device__ __forceinline__ void sts32(uint32_t a, uint32_t v) {
    asm volatile("st.shared.b32 [%0], %1;" :: "r"(a), "r"(v));
}
__device__ __forceinline__ void mma_bf16(float* c, const uint32_t* a, uint32_t b0, uint32_t b1) {
    asm volatile(
        "mma.sync.aligned.m16n8k16.row.col.f32.bf16.bf16.f32 "
        "{%0,%1,%2,%3}, {%4,%5,%6,%7}, {%8,%9}, {%0,%1,%2,%3};"
        : "+f"(c[0]), "+f"(c[1]), "+f"(c[2]), "+f"(c[3])
        : "r"(a[0]), "r"(a[1]), "r"(a[2]), "r"(a[3]), "r"(b0), "r"(b1));
}
__device__ __forceinline__ void cpa16(uint32_t d, const void* s) {
    asm volatile("cp.async.ca.shared.global [%0], [%1], 16;" :: "r"(d), "l"(s));
}
#define CP_COMMIT() asm volatile("cp.async.commit_group;" ::: "memory")
#define CP_WAIT1()  asm volatile("cp.async.wait_group 1;" ::: "memory")

__device__ __forceinline__ void split2(float a, float b, uint32_t& hi, uint32_t& lo) {
    __nv_bfloat16 ha = __float2bfloat16(a), hb = __float2bfloat16(b);
    __nv_bfloat16 la = __float2bfloat16(a - __bfloat162float(ha));
    __nv_bfloat16 lb = __float2bfloat16(b - __bfloat162float(hb));
    __nv_bfloat162 th = __halves2bfloat162(ha, hb), tl = __halves2bfloat162(la, lb);
    hi = *reinterpret_cast<uint32_t*>(&th);
    lo = *reinterpret_cast<uint32_t*>(&tl);
}
__device__ __forceinline__ float qred(float v) {
    v += __shfl_xor_sync(0xffffffffu, v, 1);
    v += __shfl_xor_sync(0xffffffffu, v, 2);
    return v;
}

// fill one K=32 chunk: rows [0,nrows) of [N][K] hi/lo planes -> stage (rows padded to 40 elems)
__device__ __forceinline__ void cp_fill(uint32_t dst, const __nv_bfloat16* __restrict__ hi,
                                        const __nv_bfloat16* __restrict__ lo,
                                        int nrows, int kstride, int kbase, int tid) {
    int total = nrows * 4;
    for (int i = tid; i < total; i += 256) {
        int n = i >> 2, seg = i & 3;
        uint32_t d = dst + (uint32_t)n * 80u + (uint32_t)seg * 16u;
        cpa16(d,            (const char*)(hi + n * kstride + kbase) + seg * 16);
        cpa16(d + PLANE_B,  (const char*)(lo + n * kstride + kbase) + seg * 16);
    }
}

// GEMM over M=128 (8 warps x 16 rows), N = NT*8, K = nchunks*32, 3-product bf16 split.
// Protocol: two chunk-groups pre-committed by caller; each iter: wait<=1, sync, compute,
// sync, commit next (possibly empty) group.
template<int NT>
__device__ __forceinline__ void gemm_run(float (*C)[4], int nchunks, int nrows_b,
                                         const __nv_bfloat16* __restrict__ shi,
                                         const __nv_bfloat16* __restrict__ slo,
                                         int kstride, uint32_t aHi, uint32_t aLo,
                                         uint32_t bBase, int tid) {
    const int lane = tid & 31, wid = tid >> 5;
    const uint32_t arow = (uint32_t)(16 * wid + (lane >> 2)) * AROW + (uint32_t)(lane & 3) * 4u;
    const uint32_t brow = (uint32_t)(lane >> 2) * 80u + (uint32_t)(lane & 3) * 4u;
    #pragma unroll
    for (int t = 0; t < NT; t++) { C[t][0] = 0.f; C[t][1] = 0.f; C[t][2] = 0.f; C[t][3] = 0.f; }
    #pragma unroll 1
    for (int ch = 0; ch < nchunks; ch++) {
        CP_WAIT1();
        __syncthreads();
        uint32_t bs = bBase + (uint32_t)(ch & 1) * STAGE_B;
        #pragma unroll
        for (int k16 = 0; k16 < 2; k16++) {
            uint32_t kb = (uint32_t)(ch * 32 + k16 * 16) * 2u;
            uint32_t ah = aHi + arow + kb, al = aLo + arow + kb;
            uint32_t a_hi[4], a_lo[4];
            a_hi[0] = lds32(ah);                a_hi[1] = lds32(ah + 8 * AROW);
            a_hi[2] = lds32(ah + 16);           a_hi[3] = lds32(ah + 8 * AROW + 16);
            a_lo[0] = lds32(al);                a_lo[1] = lds32(al + 8 * AROW);
            a_lo[2] = lds32(al + 16);           a_lo[3] = lds32(al + 8 * AROW + 16);
            uint32_t bk = bs + brow + (uint32_t)k16 * 32u;
            #pragma unroll
            for (int nt = 0; nt < NT; nt++) {
                uint32_t ba = bk + (uint32_t)nt * 640u;
                uint32_t bh0 = lds32(ba),            bh1 = lds32(ba + 16);
                uint32_t bl0 = lds32(ba + PLANE_B),  bl1 = lds32(ba + PLANE_B + 16);
                mma_bf16(C[nt], a_hi, bh0, bh1);
                mma_bf16(C[nt], a_hi, bl0, bl1);
                mma_bf16(C[nt], a_lo, bh0, bh1);
            }
        }
        __syncthreads();
        if (ch + 2 < nchunks)
            cp_fill(bBase + (uint32_t)(ch & 1) * STAGE_B, shi, slo, nrows_b, kstride,
                    (ch + 2) * 32, tid);
        CP_COMMIT();
    }
}

// ---------------- aux kernels ----------------
__global__ void precompute_kernel(const float* __restrict__ t_rand) {
    __shared__ float zsh[NSAMP];
    int i = threadIdx.x;
    float t   = (float)i / 63.0f;
    float z0  = NEAR_ * (1.0f - t) + FAR_ * t;
    float tn  = (float)(i + 1) / 63.0f;
    float z0n = NEAR_ * (1.0f - tn) + FAR_ * tn;
    float tp  = (float)(i - 1) / 63.0f;
    float z0p = NEAR_ * (1.0f - tp) + FAR_ * tp;
    float upper = (i < NSAMP - 1) ? 0.5f * (z0 + z0n) : z0;
    float lower = (i > 0) ? 0.5f * (z0p + z0) : z0;
    float z = lower + (upper - lower) * t_rand[i];
    zsh[i] = z;
    g_z[i] = z;
    __syncthreads();
    g_dists[i] = (i < NSAMP - 1) ? (zsh[i + 1] - zsh[i]) : DINF;
}

__global__ void prep_weights(const float* __restrict__ w1,
                             const float* __restrict__ w2,
                             const float* __restrict__ wd) {
    int idx = blockIdx.x * 256 + threadIdx.x;
    float v; __nv_bfloat16 *ph, *pl; int o;
    if (idx < 16384) {
        int n = idx >> 6, k = idx & 63;
        v = (k < 63) ? w1[k * 256 + n] : 0.0f;
        ph = g_w1T_hi; pl = g_w1T_lo; o = idx;
    } else if (idx < 16384 + 65536) {
        int t = idx - 16384; int n = t >> 8, k = t & 255;
        v = w2[k * 256 + n];
        ph = g_w2T_hi; pl = g_w2T_lo; o = t;
    } else if (idx < 16384 + 65536 + 32768) {
        int t = idx - 16384 - 65536; int n = t >> 8, k = t & 255;
        v = wd[k * 128 + n];
        ph = g_wdT_hi; pl = g_wdT_lo; o = t;
    } else return;
    __nv_bfloat16 h = __float2bfloat16(v);
    ph[o] = h;
    pl[o] = __float2bfloat16(v - __bfloat162float(h));
}

// ---------------- main fused kernel ----------------
__global__ void __launch_bounds__(256, 1) nerf_hmma(
    const float* __restrict__ c2w,
    const float* __restrict__ b1g,  const float* __restrict__ b2g,
    const float* __restrict__ wsigg,const float* __restrict__ bsigg,
    const float* __restrict__ wdirg,const float* __restrict__ bdirg,
    const float* __restrict__ wrgbg,const float* __restrict__ brgbg,
    float* __restrict__ out)
{
    extern __shared__ char smraw[];
    float* smf = (float*)smraw;
    const uint32_t base = smem_u32(smraw);
    const uint32_t aHi = base + A_HI_OFF, aLo = base + A_LO_OFF, bB = base + B_OFF;
    const int tid = threadIdx.x, lane = tid & 31, wid = tid >> 5;
    const int ray0 = blockIdx.x * 2;

    // prefetch GEMM1's two K-chunks of w1T immediately (2 groups)
    cp_fill(bB,           g_w1T_hi, g_w1T_lo, 256, 64, 0,  tid); CP_COMMIT();
    cp_fill(bB + STAGE_B, g_w1T_hi, g_w1T_lo, 256, 64, 32, tid); CP_COMMIT();

    // stage small tensors
    for (int i = tid; i < 256; i += 256) {
        smf[F_B1 + i]   = b1g[i];
        smf[F_B2 + i]   = b2g[i];
        smf[F_WSIG + i] = wsigg[i];
    }
    for (int i = tid; i < 384; i += 256) smf[F_WRGB + i] = wrgbg[i];
    if (tid < 2) {
        int ray = ray0 + tid;
        int c = ray % 100, rw = ray / 100;
        float dx = ((float)c - 50.0f) / FXc;
        float dy = -(((float)rw - 50.0f) / FXc);
        float d0 = dx * c2w[0] + dy * c2w[1] - c2w[2];
        float d1 = dx * c2w[4] + dy * c2w[5] - c2w[6];
        float d2 = dx * c2w[8] + dy * c2w[9] - c2w[10];
        float nrm = sqrtf(d0 * d0 + d1 * d1 + d2 * d2);
        float* R = smf + F_RAY + tid * 12;
        R[0] = c2w[3]; R[1] = c2w[7]; R[2] = c2w[11];
        R[3] = d0; R[4] = d1; R[5] = d2;
        R[6] = d0 / nrm; R[7] = d1 / nrm; R[8] = d2 / nrm;
        R[9] = nrm;
    }
    __syncthreads();

    // enc_dir (27 per ray)
    if (tid < 54) {
        int rr = tid / 27, dd = tid - rr * 27;
        const float* vv = smf + F_RAY + rr * 12 + 6;
        float val;
        if (dd < 3) val = vv[dd];
        else {
            int u = dd - 3, l = u / 6, r6 = u % 6, cc = r6 % 3;
            float x = vv[cc] * (float)(1 << l);
            val = (r6 < 3) ? sinf(x) : cosf(x);
        }
        smf[F_EDIR + rr * 32 + dd] = val;
    }

    // posenc(pts): 128 rows x 63 dims -> A planes (cols 0..63, col 63 zero)
    if (tid < 128) {
        int rr = tid >> 6, s = tid & 63;
        float z = g_z[s];
        const float* R = smf + F_RAY + rr * 12;
        float v[64];
        float f0 = fmaf(R[3], z, R[0]);
        float f1 = fmaf(R[4], z, R[1]);
        float f2 = fmaf(R[5], z, R[2]);
        v[0] = f0; v[1] = f1; v[2] = f2;
        #pragma unroll
        for (int l = 0; l < 10; l++) {
            float s0, c0, s1, c1, s2, c2;
            sincosf(f0, &s0, &c0); sincosf(f1, &s1, &c1); sincosf(f2, &s2, &c2);
            int b = 3 + l * 6;
            v[b] = s0; v[b + 1] = s1; v[b + 2] = s2;
            v[b + 3] = c0; v[b + 4] = c1; v[b + 5] = c2;
            f0 *= 2.0f; f1 *= 2.0f; f2 *= 2.0f;
        }
        v[63] = 0.0f;
        uint32_t hi2[32], lo2[32];
        #pragma unroll
        for (int i = 0; i < 32; i++) split2(v[2 * i], v[2 * i + 1], hi2[i], lo2[i]);
        uint32_t ro = (uint32_t)tid * AROW;
        const uint4* h4 = (const uint4*)hi2;
        const uint4* l4 = (const uint4*)lo2;
        #pragma unroll
        for (int q = 0; q < 8; q++) {
            *(uint4*)(smraw + (A_HI_OFF + ro) + q * 16) = h4[q];
            *(uint4*)(smraw + (A_LO_OFF + ro) + q * 16) = l4[q];
        }
    }
    // (gemm_run's first internal barrier orders enc writes vs fragment reads)

    float C[32][4];

    // ---------------- GEMM1: h1 = relu(enc @ w1 + b1), N=256, K=64 ----------------
    gemm_run<32>(C, 2, 256, g_w1T_hi, g_w1T_lo, 64, aHi, aLo, bB, tid);
    {   // epilogue: bias+relu+split -> A planes (all reads done at loop's trailing barrier)
        #pragma unroll
        for (int nt = 0; nt < 32; nt++) {
            int col = nt * 8 + 2 * (lane & 3);
            float2 bb = *(float2*)(smf + F_B1 + col);
            float v0 = fmaxf(C[nt][0] + bb.x, 0.f), v1 = fmaxf(C[nt][1] + bb.y, 0.f);
            float v2 = fmaxf(C[nt][2] + bb.x, 0.f), v3 = fmaxf(C[nt][3] + bb.y, 0.f);
            uint32_t h0, l0, h1w, l1w;
            split2(v0, v1, h0, l0); split2(v2, v3, h1w, l1w);
            uint32_t o0 = (uint32_t)(16 * wid + (lane >> 2)) * AROW + (uint32_t)col * 2u;
            uint32_t o1 = o0 + 8 * AROW;
            sts32(aHi + o0, h0);  sts32(aLo + o0, l0);
            sts32(aHi + o1, h1w); sts32(aLo + o1, l1w);
        }
    }
    // prefetch GEMM2 chunks 0,1
    cp_fill(bB,           g_w2T_hi, g_w2T_lo, 256, 256, 0,  tid); CP_COMMIT();
    cp_fill(bB + STAGE_B, g_w2T_hi, g_w2T_lo, 256, 256, 32, tid); CP_COMMIT();
    // dir-head rank-1 bias dc[2][128] (overlaps with prefetch latency)
    {
        int j = tid & 127, rr = tid >> 7;
        float acc = bdirg[j];
        #pragma unroll
        for (int dd = 0; dd < 27; dd++)
            acc = fmaf(smf[F_EDIR + rr * 32 + dd], wdirg[(256 + dd) * 128 + j], acc);
        smf[F_DC + rr * 128 + j] = acc;
    }

    // ---------------- GEMM2: h2 = relu(h1 @ w2 + b2), N=256, K=256 ----------------
    gemm_run<32>(C, 8, 256, g_w2T_hi, g_w2T_lo, 256, aHi, aLo, bB, tid);
    {   // epilogue: bias+relu, fused sigma head, split -> A planes
        float sl = 0.f, sh = 0.f;
        #pragma unroll
        for (int nt = 0; nt < 32; nt++) {
            int col = nt * 8 + 2 * (lane & 3);
            float2 bb = *(float2*)(smf + F_B2 + col);
            float2 ws = *(float2*)(smf + F_WSIG + col);
            float v0 = fmaxf(C[nt][0] + bb.x, 0.f), v1 = fmaxf(C[nt][1] + bb.y, 0.f);
            float v2 = fmaxf(C[nt][2] + bb.x, 0.f), v3 = fmaxf(C[nt][3] + bb.y, 0.f);
            sl = fmaf(v0, ws.x, fmaf(v1, ws.y, sl));
            sh = fmaf(v2, ws.x, fmaf(v3, ws.y, sh));
            uint32_t h0, l0, h1w, l1w;
            split2(v0, v1, h0, l0); split2(v2, v3, h1w, l1w);
            uint32_t o0 = (uint32_t)(16 * wid + (lane >> 2)) * AROW + (uint32_t)col * 2u;
            uint32_t o1 = o0 + 8 * AROW;
            sts32(aHi + o0, h0);  sts32(aLo + o0, l0);
            sts32(aHi + o1, h1w); sts32(aLo + o1, l1w);
        }
        sl = qred(sl); sh = qred(sh);
        if ((lane & 3) == 0) {
            float bs0 = bsigg[0];
            smf[F_SIG + 16 * wid + (lane >> 2)]     = sl + bs0;
            smf[F_SIG + 16 * wid + (lane >> 2) + 8] = sh + bs0;
        }
    }
    // prefetch GEMM3 chunks 0,1
    cp_fill(bB,           g_wdT_hi, g_wdT_lo, 128, 256, 0,  tid); CP_COMMIT();
    cp_fill(bB + STAGE_B, g_wdT_hi, g_wdT_lo, 128, 256, 32, tid); CP_COMMIT();

    // ---------------- GEMM3: hd = relu(h2 @ w_dir[0:256] + dc), N=128, K=256 --------
    gemm_run<16>(C, 8, 128, g_wdT_hi, g_wdT_lo, 256, aHi, aLo, bB, tid);
    {   // epilogue: fused rgb head straight from fragments
        int row = 16 * wid + (lane >> 2);
        int ray = row >> 6;
        const float* dcp = smf + F_DC + ray * 128;
        float r0 = 0.f, g0 = 0.f, b0 = 0.f, r1 = 0.f, g1 = 0.f, b1v = 0.f;
        #pragma unroll
        for (int nt = 0; nt < 16; nt++) {
            int col = nt * 8 + 2 * (lane & 3);
            float d0 = dcp[col], d1 = dcp[col + 1];
            float h0 = fmaxf(C[nt][0] + d0, 0.f), h1 = fmaxf(C[nt][1] + d1, 0.f);
            float h2 = fmaxf(C[nt][2] + d0, 0.f), h3 = fmaxf(C[nt][3] + d1, 0.f);
            const float* w0 = smf + F_WRGB + col * 3;
            const float* w1v = w0 + 3;
            r0  = fmaf(h0, w0[0], fmaf(h1, w1v[0], r0));
            g0  = fmaf(h0, w0[1], fmaf(h1, w1v[1], g0));
            b0  = fmaf(h0, w0[2], fmaf(h1, w1v[2], b0));
            r1  = fmaf(h2, w0[0], fmaf(h3, w1v[0], r1));
            g1  = fmaf(h2, w0[1], fmaf(h3, w1v[1], g1));
            b1v = fmaf(h2, w0[2], fmaf(h3, w1v[2], b1v));
        }
        r0 = qred(r0); g0 = qred(g0); b0 = qred(b0);
        r1 = qred(r1); g1 = qred(g1); b1v = qred(b1v);
        if ((lane & 3) == 0) {
            float br = brgbg[0], bg = brgbg[1], bbv = brgbg[2];
            smf[F_RGB + row * 3 + 0] = 1.0f / (1.0f + expf(-(r0 + br)));
            smf[F_RGB + row * 3 + 1] = 1.0f / (1.0f + expf(-(g0 + bg)));
            smf[F_RGB + row * 3 + 2] = 1.0f / (1.0f + expf(-(b0 + bbv)));
            smf[F_RGB + (row + 8) * 3 + 0] = 1.0f / (1.0f + expf(-(r1 + br)));
            smf[F_RGB + (row + 8) * 3 + 1] = 1.0f / (1.0f + expf(-(g1 + bg)));
            smf[F_RGB + (row + 8) * 3 + 2] = 1.0f / (1.0f + expf(-(b1v + bbv)));
        }
    }
    __syncthreads();

    // ---------------- compositing (2 rays) ----------------
    if (tid < 2) {
        float nrm = smf[F_RAY + tid * 12 + 9];
        float T = 1.0f, r = 0.0f, g = 0.0f, b = 0.0f;
        #pragma unroll 1
        for (int s = 0; s < NSAMP; s++) {
            int m = tid * 64 + s;
            float sg = fmaxf(smf[F_SIG + m], 0.0f);
            float a = 1.0f - expf(-sg * g_dists[s] * nrm);
            float w = a * T;
            r = fmaf(w, smf[F_RGB + m * 3 + 0], r);
            g = fmaf(w, smf[F_RGB + m * 3 + 1], g);
            b = fmaf(w, smf[F_RGB + m * 3 + 2], b);
            T *= (1.0f - a);
        }
        out[(ray0 + tid) * 3 + 0] = r;
        out[(ray0 + tid) * 3 + 1] = g;
        out[(ray0 + tid) * 3 + 2] = b;
    }
}

extern "C" void kernel_launch(void* const* d_in, const int* in_sizes, int n_in,
                              void* d_out, int out_size) {
    const float* c2w    = (const float*)d_in[0];
    const float* t_rand = (const float*)d_in[1];
    const float* w1     = (const float*)d_in[2];
    const float* b1     = (const float*)d_in[3];
    const float* w2     = (const float*)d_in[4];
    const float* b2     = (const float*)d_in[5];
    const float* w_sig  = (const float*)d_in[6];
    const float* b_sig  = (const float*)d_in[7];
    const float* w_dir  = (const float*)d_in[8];
    const float* b_dir  = (const float*)d_in[9];
    const float* w_rgb  = (const float*)d_in[10];
    const float* b_rgb  = (const float*)d_in[11];
    float* out = (float*)d_out;

    cudaFuncSetAttribute(nerf_hmma, cudaFuncAttributeMaxDynamicSharedMemorySize, SMEM_BYTES);

    precompute_kernel<<<1, NSAMP>>>(t_rand);
    prep_weights<<<448, 256>>>(w1, w2, w_dir);
    nerf_hmma<<<NBLOCKS, 256, SMEM_BYTES>>>(c2w, b1, b2, w_sig, b_sig,
                                            w_dir, b_dir, w_rgb, b_rgb, out);
}